// round 13
// baseline (speedup 1.0000x reference)
#include <cuda_runtime.h>
#include <cstdint>
#include <math.h>

#define L_SEQ  2048
#define BATCH  2
#define DM     1024
#define NH     16
#define DK     64
#define E3     3072
#define MROWS  (L_SEQ * BATCH)
#define HB     (NH * BATCH)     // 32

// Scratch: all tensor-core inputs stored as TF32 BIT PATTERNS (uint32).
__device__ uint32_t g_Xt[MROWS * DM];       // tf32(X)
__device__ uint32_t g_Wt[E3 * DM];          // tf32(W)
__device__ uint32_t g_Q[HB * L_SEQ * DK];   // [hb][l][d]  tf32(q * 0.125)
__device__ uint32_t g_K[HB * L_SEQ * DK];   // [hb][l][d]  tf32(k)
__device__ uint32_t g_V[HB * L_SEQ * DK];   // [hb][l][d]  tf32(v)

// ---------------------------------------------------------------------------
// helpers
// ---------------------------------------------------------------------------
__device__ __forceinline__ uint32_t cvt_tf32(float x) {
    uint32_t u;
    asm("cvt.rna.tf32.f32 %0, %1;" : "=r"(u) : "f"(x));
    return u;
}

// D += A(16x8) * B(8x8), tf32 inputs, f32 accum
__device__ __forceinline__ void mma_tf32(float* d, const uint32_t* a, const uint32_t* b) {
    asm volatile(
        "mma.sync.aligned.m16n8k8.row.col.f32.tf32.tf32.f32 "
        "{%0,%1,%2,%3}, {%4,%5,%6,%7}, {%8,%9}, {%0,%1,%2,%3};"
        : "+f"(d[0]), "+f"(d[1]), "+f"(d[2]), "+f"(d[3])
        : "r"(a[0]), "r"(a[1]), "r"(a[2]), "r"(a[3]), "r"(b[0]), "r"(b[1]));
}

__device__ __forceinline__ uint32_t smem_u32(const void* p) {
    uint32_t a;
    asm("{ .reg .u64 t; cvta.to.shared.u64 t, %1; cvt.u32.u64 %0, t; }"
        : "=r"(a) : "l"(p));
    return a;
}

#define CP_ASYNC16(dst, src) \
    asm volatile("cp.async.ca.shared.global [%0], [%1], 16;" :: "r"(dst), "l"(src))
#define CP_COMMIT() asm volatile("cp.async.commit_group;" ::: "memory")
#define CP_WAIT0()  asm volatile("cp.async.wait_group 0;" ::: "memory")
#define CP_WAIT1()  asm volatile("cp.async.wait_group 1;" ::: "memory")

// ---------------------------------------------------------------------------
// Kernel 0: prepass — convert X and W to tf32 bit patterns (hoists the cvt
// out of the QKV k-loop where each element is re-staged 24-32 times).
// ---------------------------------------------------------------------------
#define PRE_TOTAL4 ((MROWS * DM + E3 * DM) / 4)   // float4 slots: 1,835,008
__global__ __launch_bounds__(256) void prepass_kernel(
    const float* __restrict__ X, const float* __restrict__ W)
{
    int idx = blockIdx.x * 256 + threadIdx.x;
    if (idx >= PRE_TOTAL4) return;
    const int xn4 = MROWS * DM / 4;
    if (idx < xn4) {
        float4 v = *(const float4*)(X + (size_t)idx * 4);
        *(uint4*)&g_Xt[(size_t)idx * 4] =
            make_uint4(cvt_tf32(v.x), cvt_tf32(v.y), cvt_tf32(v.z), cvt_tf32(v.w));
    } else {
        int k = idx - xn4;
        float4 v = *(const float4*)(W + (size_t)k * 4);
        *(uint4*)&g_Wt[(size_t)k * 4] =
            make_uint4(cvt_tf32(v.x), cvt_tf32(v.y), cvt_tf32(v.z), cvt_tf32(v.w));
    }
}

// ---------------------------------------------------------------------------
// Kernel 1: QKV projection (tf32 mma.sync) with FUSED RoPE epilogue.
// CTA tile 128x128, BK=32, THREE-stage cp.async circular buffer, one
// __syncthreads per k-step. 8 warps (2x4), warp tile 64x32, stride-36 smem.
// Epilogue: RoPE, fold 1/8 scale into Q, store TF32 bit patterns.
// ---------------------------------------------------------------------------
#define QBUF 4608                 // words per (A+B) stage pair half: 128*36
#define QKV_SMEM (3 * 2 * QBUF * 4)   // 110592 B
__global__ __launch_bounds__(256, 2) void qkv_mma_kernel()
{
    extern __shared__ uint32_t sm32[];
    // layout: stage p in [0,3): A at p*2*QBUF, B at p*2*QBUF + QBUF
    const uint32_t sbase = smem_u32(sm32);

    const int tid  = threadIdx.x;
    const int lane = tid & 31;
    const int w    = tid >> 5;
    const int wm   = w >> 2;       // 0..1
    const int wn   = w & 3;        // 0..3
    const int g    = lane >> 2;    // 0..7
    const int j    = lane & 3;     // 0..3

    const int m0 = blockIdx.y * 128;
    const int n0 = blockIdx.x * 128;

    const uint32_t* Xt = g_Xt;
    const uint32_t* Wt = g_Wt;

    // staging map: idx = tid + it*256 (it 0..3): r = idx>>3 (0..127), c4=(idx&7)*4
    const int st_r = tid >> 3;
    const int st_c = (tid & 7) * 4;

#define QKV_STAGE(p, k0)                                                        \
    {                                                                           \
        uint32_t ab = sbase + ((p) * 2 * QBUF) * 4;                             \
        uint32_t bb = ab + QBUF * 4;                                            \
        _Pragma("unroll")                                                       \
        for (int it = 0; it < 4; it++) {                                        \
            int r = st_r + it * 32;                                             \
            CP_ASYNC16(ab + (r * 36 + st_c) * 4,                                \
                       Xt + (size_t)(m0 + r) * DM + (k0) + st_c);               \
            CP_ASYNC16(bb + (r * 36 + st_c) * 4,                                \
                       Wt + (size_t)(n0 + r) * DM + (k0) + st_c);               \
        }                                                                       \
        CP_COMMIT();                                                            \
    }

    float acc[4][4][4];
#pragma unroll
    for (int mt = 0; mt < 4; mt++)
#pragma unroll
        for (int nt = 0; nt < 4; nt++)
#pragma unroll
            for (int e = 0; e < 4; e++) acc[mt][nt][e] = 0.f;

    QKV_STAGE(0, 0);
    QKV_STAGE(1, 32);

    for (int s = 0; s < 32; s++) {
        if (s + 1 < 32) CP_WAIT1(); else CP_WAIT0();
        __syncthreads();   // stage s visible to all; all warps done with mma(s-1)
        if (s + 2 < 32) QKV_STAGE((s + 2) % 3, (s + 2) * 32);

        const uint32_t* Ab = sm32 + ((s % 3) * 2 * QBUF);
        const uint32_t* Bb = Ab + QBUF;
#pragma unroll
        for (int ks = 0; ks < 4; ks++) {
            const int kk = ks * 8;
            uint32_t af[4][4];
#pragma unroll
            for (int mt = 0; mt < 4; mt++) {
                int row = wm * 64 + mt * 16 + g;
                af[mt][0] = Ab[row * 36 + kk + j];
                af[mt][1] = Ab[(row + 8) * 36 + kk + j];
                af[mt][2] = Ab[row * 36 + kk + j + 4];
                af[mt][3] = Ab[(row + 8) * 36 + kk + j + 4];
            }
#pragma unroll
            for (int nt = 0; nt < 4; nt++) {
                int col = wn * 32 + nt * 8 + g;
                uint32_t bf[2] = { Bb[col * 36 + kk + j], Bb[col * 36 + kk + j + 4] };
#pragma unroll
                for (int mt = 0; mt < 4; mt++)
                    mma_tf32(acc[mt][nt], af[mt], bf);
            }
        }
    }

    // ---- fused RoPE on accumulators (q and k columns only) ----
    if ((wn & 1) == 0) {
        float thc[2][2];
#pragma unroll
        for (int nt = 0; nt < 2; nt++)
#pragma unroll
            for (int e = 0; e < 2; e++) {
                int d = nt * 8 + 2 * j + e;
                thc[nt][e] = powf(10000.0f, -(float)d * (1.0f / 16.0f));
            }
#pragma unroll
        for (int nt = 0; nt < 2; nt++) {
            int col = n0 + wn * 32 + nt * 8 + 2 * j;
            int h   = col / 192;
            int jj  = col - h * 192;
            int t   = jj >> 6;
            if (t < 2) {   // q or k column
#pragma unroll
                for (int mt = 0; mt < 4; mt++) {
#pragma unroll
                    for (int rr = 0; rr < 2; rr++) {
                        int row = m0 + wm * 64 + mt * 16 + g + rr * 8;
                        float lf = (float)(row >> 1);
#pragma unroll
                        for (int e = 0; e < 2; e++) {
                            float sn, cs;
                            sincosf(lf * thc[nt][e], &sn, &cs);
                            float x1 = acc[mt][nt][rr * 2 + e];
                            float x2 = acc[mt][nt + 2][rr * 2 + e];
                            acc[mt][nt][rr * 2 + e]     = x1 * cs - x2 * sn;
                            acc[mt][nt + 2][rr * 2 + e] = x2 * cs + x1 * sn;
                        }
                    }
                }
            }
        }
    }

    // ---- epilogue scatter: convert to tf32 bits (Q gets 1/8 scale) ----
#pragma unroll
    for (int mt = 0; mt < 4; mt++) {
#pragma unroll
        for (int nt = 0; nt < 4; nt++) {
            int col = n0 + wn * 32 + nt * 8 + 2 * j;
            int h   = col / 192;
            int jj  = col - h * 192;
            int t   = jj >> 6;
            int d   = jj & 63;
#pragma unroll
            for (int rr = 0; rr < 2; rr++) {
                int row = m0 + wm * 64 + mt * 16 + g + rr * 8;
                int l = row >> 1, b = row & 1;
                int hb = h * 2 + b;
                float v0 = acc[mt][nt][rr * 2], v1 = acc[mt][nt][rr * 2 + 1];
                if (t == 0) { v0 *= 0.125f; v1 *= 0.125f; }
                uint2 u = make_uint2(cvt_tf32(v0), cvt_tf32(v1));
                uint32_t* dst = (t == 0) ? g_Q : (t == 1) ? g_K : g_V;
                *(uint2*)&dst[(((size_t)hb * L_SEQ) + l) * DK + d] = u;
            }
        }
    }
}

// ---------------------------------------------------------------------------
// Kernel 2: fused flash attention, tf32 mma.sync. (unchanged from R11)
// CTA: 128 q rows x one (h,b). 8 warps x 16 q-rows, 2 CTAs/SM.
// K/V double-buffered via cp.async; ONE __syncthreads per 64-key chunk.
// ---------------------------------------------------------------------------
#define KST 68
#define VST 72
#define KBUF (64 * KST)
#define VBUF (64 * VST)
#define FLASH_SMEM ((2 * KBUF + 2 * VBUF + 128 * KST) * 4)   // 106496 B

__global__ __launch_bounds__(256, 2) void flash_kernel(float* __restrict__ out)
{
    extern __shared__ uint32_t fsm[];
    uint32_t* Kb = fsm;                       // [2][64][KST]
    uint32_t* Vb = fsm + 2 * KBUF;            // [2][64][VST]
    uint32_t* Ps = fsm + 2 * KBUF + 2 * VBUF; // [128][KST]

    const uint32_t kb_s = smem_u32(Kb);
    const uint32_t vb_s = smem_u32(Vb);

    const int tid  = threadIdx.x;
    const int lane = tid & 31;
    const int w    = tid >> 5;     // 0..7
    const int g    = lane >> 2;
    const int j    = lane & 3;

    const int q0 = blockIdx.x * 128;
    const int hb = blockIdx.y;
    const int h  = hb >> 1, b = hb & 1;

    const uint32_t* Qg = g_Q + (size_t)hb * L_SEQ * DK;
    const uint32_t* Kg = g_K + (size_t)hb * L_SEQ * DK;
    const uint32_t* Vg = g_V + (size_t)hb * L_SEQ * DK;

    const int st_r = tid >> 4;
    const int st_c = (tid & 15) * 4;

#define FL_STAGE(buf, roff)                                                     \
    {                                                                           \
        _Pragma("unroll")                                                       \
        for (int it = 0; it < 4; it++) {                                        \
            int r = st_r + it * 16;                                             \
            CP_ASYNC16(kb_s + ((buf) * KBUF + r * KST + st_c) * 4,              \
                       Kg + ((roff) + r) * DK + st_c);                          \
            CP_ASYNC16(vb_s + ((buf) * VBUF + r * VST + st_c) * 4,              \
                       Vg + ((roff) + r) * DK + st_c);                          \
        }                                                                       \
        CP_COMMIT();                                                            \
    }

    // Q fragments (already scaled tf32 bits)
    uint32_t qa[8][4];
    {
        int r0 = q0 + w * 16 + g;
#pragma unroll
        for (int ks = 0; ks < 8; ks++) {
            int c = ks * 8 + j;
            qa[ks][0] = Qg[(size_t)r0 * DK + c];
            qa[ks][1] = Qg[(size_t)(r0 + 8) * DK + c];
            qa[ks][2] = Qg[(size_t)r0 * DK + c + 4];
            qa[ks][3] = Qg[(size_t)(r0 + 8) * DK + c + 4];
        }
    }

    float o[8][4];
#pragma unroll
    for (int nt = 0; nt < 8; nt++)
#pragma unroll
        for (int e = 0; e < 4; e++) o[nt][e] = 0.f;
    float mrow0 = -1e30f, mrow1 = -1e30f;
    float lrow0 = 0.f, lrow1 = 0.f;

    FL_STAGE(0, (size_t)0);

    for (int kc = 0; kc < L_SEQ / 64; kc++) {
        CP_WAIT0();
        __syncthreads();

        if (kc + 1 < L_SEQ / 64) FL_STAGE((kc + 1) & 1, (size_t)(kc + 1) * 64);

        const uint32_t* Ks = Kb + (kc & 1) * KBUF;
        const uint32_t* Vs = Vb + (kc & 1) * VBUF;

        // S = Q K^T
        float s[8][4];
#pragma unroll
        for (int nt = 0; nt < 8; nt++)
#pragma unroll
            for (int e = 0; e < 4; e++) s[nt][e] = 0.f;
#pragma unroll
        for (int ks = 0; ks < 8; ks++) {
            const int kk = ks * 8;
#pragma unroll
            for (int nt = 0; nt < 8; nt++) {
                uint32_t bf[2] = { Ks[(nt * 8 + g) * KST + kk + j],
                                   Ks[(nt * 8 + g) * KST + kk + j + 4] };
                mma_tf32(s[nt], qa[ks], bf);
            }
        }

        // online softmax
        float mx0 = -1e30f, mx1 = -1e30f;
#pragma unroll
        for (int nt = 0; nt < 8; nt++) {
            mx0 = fmaxf(mx0, fmaxf(s[nt][0], s[nt][1]));
            mx1 = fmaxf(mx1, fmaxf(s[nt][2], s[nt][3]));
        }
        mx0 = fmaxf(mx0, __shfl_xor_sync(0xffffffffu, mx0, 1));
        mx0 = fmaxf(mx0, __shfl_xor_sync(0xffffffffu, mx0, 2));
        mx1 = fmaxf(mx1, __shfl_xor_sync(0xffffffffu, mx1, 1));
        mx1 = fmaxf(mx1, __shfl_xor_sync(0xffffffffu, mx1, 2));

        float mn0 = fmaxf(mrow0, mx0), mn1 = fmaxf(mrow1, mx1);
        float al0 = __expf(mrow0 - mn0), al1 = __expf(mrow1 - mn1);
        mrow0 = mn0; mrow1 = mn1;

        float rs0 = 0.f, rs1 = 0.f;
#pragma unroll
        for (int nt = 0; nt < 8; nt++) {
            s[nt][0] = __expf(s[nt][0] - mn0);
            s[nt][1] = __expf(s[nt][1] - mn0);
            s[nt][2] = __expf(s[nt][2] - mn1);
            s[nt][3] = __expf(s[nt][3] - mn1);
            rs0 += s[nt][0] + s[nt][1];
            rs1 += s[nt][2] + s[nt][3];
        }
        rs0 += __shfl_xor_sync(0xffffffffu, rs0, 1);
        rs0 += __shfl_xor_sync(0xffffffffu, rs0, 2);
        rs1 += __shfl_xor_sync(0xffffffffu, rs1, 1);
        rs1 += __shfl_xor_sync(0xffffffffu, rs1, 2);
        lrow0 = lrow0 * al0 + rs0;
        lrow1 = lrow1 * al1 + rs1;

#pragma unroll
        for (int nt = 0; nt < 8; nt++) {
            o[nt][0] *= al0; o[nt][1] *= al0;
            o[nt][2] *= al1; o[nt][3] *= al1;
        }

        // write P (warp-private rows)
        {
            int pr0 = (w * 16 + g) * KST;
            int pr1 = (w * 16 + g + 8) * KST;
#pragma unroll
            for (int nt = 0; nt < 8; nt++) {
                int c = nt * 8 + 2 * j;
                *(uint2*)&Ps[pr0 + c] = make_uint2(cvt_tf32(s[nt][0]), cvt_tf32(s[nt][1]));
                *(uint2*)&Ps[pr1 + c] = make_uint2(cvt_tf32(s[nt][2]), cvt_tf32(s[nt][3]));
            }
        }

        // O += P V
#pragma unroll
        for (int ks = 0; ks < 8; ks++) {
            const int kk = ks * 8;
            uint32_t pa[4];
            pa[0] = Ps[(w * 16 + g) * KST + kk + j];
            pa[1] = Ps[(w * 16 + g + 8) * KST + kk + j];
            pa[2] = Ps[(w * 16 + g) * KST + kk + j + 4];
            pa[3] = Ps[(w * 16 + g + 8) * KST + kk + j + 4];
#pragma unroll
            for (int nt = 0; nt < 8; nt++) {
                uint32_t bf[2] = { Vs[(kk + j) * VST + nt * 8 + g],
                                   Vs[(kk + j + 4) * VST + nt * 8 + g] };
                mma_tf32(o[nt], pa, bf);
            }
        }
    }

    // normalize and write out
    float inv0 = 1.0f / lrow0, inv1 = 1.0f / lrow1;
    int r0 = q0 + w * 16 + g;
#pragma unroll
    for (int nt = 0; nt < 8; nt++) {
        int c = nt * 8 + 2 * j;
        float2 v0 = make_float2(o[nt][0] * inv0, o[nt][1] * inv0);
        *(float2*)(out + ((size_t)r0 * BATCH + b) * DM + h * DK + c) = v0;
        float2 v1 = make_float2(o[nt][2] * inv1, o[nt][3] * inv1);
        *(float2*)(out + ((size_t)(r0 + 8) * BATCH + b) * DM + h * DK + c) = v1;
    }
}

// ---------------------------------------------------------------------------
extern "C" void kernel_launch(void* const* d_in, const int* in_sizes, int n_in,
                              void* d_out, int out_size)
{
    const float* X = (const float*)d_in[0];
    const float* W = (const float*)d_in[1];
    float* out = (float*)d_out;

    cudaFuncSetAttribute(qkv_mma_kernel,
                         cudaFuncAttributeMaxDynamicSharedMemorySize, QKV_SMEM);
    cudaFuncSetAttribute(flash_kernel,
                         cudaFuncAttributeMaxDynamicSharedMemorySize, FLASH_SMEM);

    prepass_kernel<<<(PRE_TOTAL4 + 255) / 256, 256>>>(X, W);
    qkv_mma_kernel<<<dim3(E3 / 128, MROWS / 128), 256, QKV_SMEM>>>();
    flash_kernel<<<dim3(L_SEQ / 128, HB), 256, FLASH_SMEM>>>(out);
}